// round 16
// baseline (speedup 1.0000x reference)
#include <cuda_runtime.h>
#include <cuda_bf16.h>
#include <cstdint>
#include <math.h>

#define H    4
#define NN   4096
#define CHAN 16
#define ADIM 64
#define VDIM 16
#define D    64
#define EXT  80          // 64 feature dims + 5 bias dims + zero pad (5 ksteps of 16)
#define QT   128         // query rows per CTA (32 per warp, 2 rowsets of 16)
#define KT   64          // key tile
#define NSPLIT 2
#define NT2  (NN / KT / NSPLIT)   // 32 tiles per split

#define LOG2E 1.4426950408889634f

// ---------------- device global scratch (no runtime alloc allowed) ----------
__device__ __align__(16) __nv_bfloat16 g_Qe[2][H][NN][EXT];
__device__ __align__(16) __nv_bfloat16 g_Ke[2][H][NN][EXT];
__device__ __align__(16) __nv_bfloat16 g_Vt[2][H][D][NN];
__device__ float g_pm[NSPLIT * H * NN];
__device__ float g_pl[NSPLIT * H * NN];
__device__ __align__(16) float g_pO[NSPLIT][H][NN][D];

// ---------------- helpers ---------------------------------------------------
__device__ __forceinline__ uint32_t smem_u32(const void* p) {
    uint32_t a;
    asm("{ .reg .u64 t; cvta.to.shared.u64 t, %1; cvt.u32.u64 %0, t; }" : "=r"(a) : "l"(p));
    return a;
}
__device__ __forceinline__ void ldm_x4(uint32_t* r, uint32_t addr) {
    asm volatile("ldmatrix.sync.aligned.m8n8.x4.shared.b16 {%0,%1,%2,%3}, [%4];"
                 : "=r"(r[0]), "=r"(r[1]), "=r"(r[2]), "=r"(r[3]) : "r"(addr));
}
__device__ __forceinline__ void mma16816(float* c, const uint32_t* a,
                                         uint32_t b0, uint32_t b1) {
    asm volatile("mma.sync.aligned.m16n8k16.row.col.f32.bf16.bf16.f32 "
                 "{%0,%1,%2,%3}, {%4,%5,%6,%7}, {%8,%9}, {%0,%1,%2,%3};"
                 : "+f"(c[0]), "+f"(c[1]), "+f"(c[2]), "+f"(c[3])
                 : "r"(a[0]), "r"(a[1]), "r"(a[2]), "r"(a[3]), "r"(b0), "r"(b1));
}
__device__ __forceinline__ uint32_t pack_bf16x2(float x0, float x1) {
    uint32_t r;
    asm("cvt.rn.bf16x2.f32 %0, %1, %2;" : "=r"(r) : "f"(x1), "f"(x0));
    return r;
}
__device__ __forceinline__ void pack_hilo(float x0, float x1, uint32_t& hi, uint32_t& lo) {
    asm("cvt.rn.bf16x2.f32 %0, %1, %2;" : "=r"(hi) : "f"(x1), "f"(x0));
    float f0 = __uint_as_float(hi << 16);
    float f1 = __uint_as_float(hi & 0xffff0000u);
    asm("cvt.rn.bf16x2.f32 %0, %1, %2;" : "=r"(lo) : "f"(x1 - f1), "f"(x0 - f0));
}
__device__ __forceinline__ float ex2(float x) {
    float y;
    asm("ex2.approx.f32 %0, %1;" : "=f"(y) : "f"(x));
    return y;
}
__device__ __forceinline__ void cp16(uint32_t saddr, const void* gaddr) {
    asm volatile("cp.async.ca.shared.global [%0], [%1], 16;" :: "r"(saddr), "l"(gaddr) : "memory");
}
#define CP_COMMIT() asm volatile("cp.async.commit_group;" ::: "memory")
#define CP_WAIT0()  asm volatile("cp.async.wait_group 0;"  ::: "memory")

#define KSTRIDE 176
#define VSTRIDE 144
#define KB_HL   (64 * KSTRIDE)
#define VB_HL   (64 * VSTRIDE)
#define STAGE_BYTES (2 * KB_HL + 2 * VB_HL)    // 40960
#define SMEM_BYTES  (2 * STAGE_BYTES)          // 81920

// ---------------------------------------------------------------------------
// Kernel 1: projection; staged, coalesced Q/K stores.
// grid (NN/16, H), 256 threads; thread = (channel c = tid>>4, token nl = tid&15).
// ---------------------------------------------------------------------------
#define PTOK 16
#define AXP  68
#define VXP  52
#define STP  88   // staging row stride in bf16 (176B, 16B-aligned)

__global__ __launch_bounds__(256)
void proj_kernel(const float* __restrict__ ax, const float* __restrict__ vx,
                 const float* __restrict__ pos_q, const float* __restrict__ pos_k,
                 const float* __restrict__ W_aq, const float* __restrict__ W_vq,
                 const float* __restrict__ W_ak, const float* __restrict__ W_vk,
                 const float* __restrict__ W_av, const float* __restrict__ W_vv)
{
    const int h  = blockIdx.y;
    const int n0 = blockIdx.x * PTOK;
    const int tid = threadIdx.x;

    __shared__ __align__(16) float s_wa[CHAN * ADIM];
    __shared__ __align__(16) float s_wv[CHAN * VDIM];
    __shared__ __align__(16) float s_ax[PTOK * AXP];
    __shared__ __align__(16) float s_vx[PTOK * VXP];
    __shared__ float ts[PTOK][68];
    __shared__ __align__(16) __nv_bfloat16 s_st[2][PTOK][STP];   // hi/lo staging

    for (int t = tid; t < PTOK * ADIM; t += 256)
        s_ax[(t >> 6) * AXP + (t & 63)] = ax[(size_t)n0 * ADIM + t];
    for (int t = tid; t < PTOK * VDIM * 3; t += 256)
        s_vx[(t / 48) * VXP + (t % 48)] = vx[(size_t)n0 * VDIM * 3 + t];

    const int c  = tid >> 4;
    const int nl = tid & 15;

    for (int z = 0; z < 3; z++) {
        const float* Wa = (z == 0) ? W_aq : (z == 1) ? W_ak : W_av;
        const float* Wv = (z == 0) ? W_vq : (z == 1) ? W_vk : W_vv;
        __syncthreads();     // prior-z store loop done before weights/staging reuse
        for (int t = tid; t < CHAN * ADIM; t += 256) s_wa[t] = Wa[h * CHAN * ADIM + t];
        for (int t = tid; t < CHAN * VDIM; t += 256) s_wv[t] = Wv[h * CHAN * VDIM + t];
        __syncthreads();

        const float4* a4 = (const float4*)(s_ax + nl * AXP);
        const float4* w4 = (const float4*)(s_wa + c * ADIM);
        float s0 = 0.f;
#pragma unroll
        for (int j = 0; j < ADIM / 4; j++) {
            float4 av = a4[j], wv4 = w4[j];
            s0 += wv4.x * av.x + wv4.y * av.y + wv4.z * av.z + wv4.w * av.w;
        }

        float vr[48];
        {
            const float4* v4 = (const float4*)(s_vx + nl * VXP);
#pragma unroll
            for (int j = 0; j < 12; j++) {
                float4 t = v4[j];
                vr[4*j] = t.x; vr[4*j+1] = t.y; vr[4*j+2] = t.z; vr[4*j+3] = t.w;
            }
        }
        float wvr[16];
        {
            const float4* q4 = (const float4*)(s_wv + c * VDIM);
#pragma unroll
            for (int j = 0; j < 4; j++) {
                float4 t = q4[j];
                wvr[4*j] = t.x; wvr[4*j+1] = t.y; wvr[4*j+2] = t.z; wvr[4*j+3] = t.w;
            }
        }
        float s1 = 0.f, s2 = 0.f, s3 = 0.f;
#pragma unroll
        for (int j = 0; j < VDIM; j++) {
            float w = wvr[j];
            s1 += w * vr[3*j+0]; s2 += w * vr[3*j+1]; s3 += w * vr[3*j+2];
        }

        if (z < 2) {
            float nsq = s0*s0 + s1*s1 + s2*s2 + s3*s3;
            float sc  = rsqrtf(sqrtf(1.0f + nsq));
            if (z == 0) sc *= LOG2E;
            s0 *= sc; s1 *= sc; s2 *= sc; s3 *= sc;
        }

        if (z == 2) {
            ts[nl][4*c+0] = s0; ts[nl][4*c+1] = s1; ts[nl][4*c+2] = s2; ts[nl][4*c+3] = s3;
            __syncthreads();
            for (int u = tid; u < 64 * 8; u += 256) {
                const int d = u >> 3, p = u & 7;
                uint32_t hv, lv;
                pack_hilo(ts[2*p][d], ts[2*p+1][d], hv, lv);
                *(uint32_t*)&g_Vt[0][h][d][n0 + 2*p] = hv;
                *(uint32_t*)&g_Vt[1][h][d][n0 + 2*p] = lv;
            }
            continue;
        }

        // ---- stage packed channels into smem rows (dims 4c..4c+3) ----
        {
            uint32_t h01, l01, h23, l23;
            pack_hilo(s0, s1, h01, l01);
            pack_hilo(s2, s3, h23, l23);
            *(uint2*)&s_st[0][nl][4*c] = make_uint2(h01, h23);
            *(uint2*)&s_st[1][nl][4*c] = make_uint2(l01, l23);
        }

        // ---- bias extension dims 64..79 into the same staging rows ----
        if (tid < PTOK) {
            const int nb = n0 + tid;
            float e[16];
#pragma unroll
            for (int j = 0; j < 16; j++) e[j] = 0.f;
            const float invr = 1.0f / (float)(1 << (2 * h));
            if (z == 0) {
                const float* pq = pos_q + (h * NN + nb) * 3;
                e[0] = 2.f * invr * pq[0] * LOG2E;
                e[1] = 2.f * invr * pq[1] * LOG2E;
                e[2] = 2.f * invr * pq[2] * LOG2E;
                e[3] = -invr * LOG2E;
                e[4] = -invr * LOG2E;
            } else {
                const float* pk = pos_k + (h * NN + nb) * 3;
                e[0] = pk[0]; e[1] = pk[1]; e[2] = pk[2];
                float w = pk[0]*pk[0] + pk[1]*pk[1] + pk[2]*pk[2];
                float whi = __bfloat162float(__float2bfloat16(w));
                e[3] = whi;
                e[4] = w - whi;
            }
            uint32_t ehw[8], elw[8];
#pragma unroll
            for (int p = 0; p < 8; p++) pack_hilo(e[2*p], e[2*p+1], ehw[p], elw[p]);
            ((uint4*)&s_st[0][tid][64])[0] = ((const uint4*)ehw)[0];
            ((uint4*)&s_st[0][tid][64])[1] = ((const uint4*)ehw)[1];
            ((uint4*)&s_st[1][tid][64])[0] = ((const uint4*)elw)[0];
            ((uint4*)&s_st[1][tid][64])[1] = ((const uint4*)elw)[1];
        }
        __syncthreads();

        // ---- coalesced store: 2 planes x 16 rows x 10 uint4 = 320 ----
        for (int u = tid; u < 2 * PTOK * 10; u += 256) {
            const int pl = u / 160;
            const int rem = u - pl * 160;
            const int rw = rem / 10, w = rem - rw * 10;
            __nv_bfloat16* base = (z == 0) ? &g_Qe[pl][h][n0 + rw][0]
                                           : &g_Ke[pl][h][n0 + rw][0];
            ((uint4*)base)[w] = ((const uint4*)&s_st[pl][rw][0])[w];
        }
    }
}

// ---------------------------------------------------------------------------
// Kernel 2: HMMA flash attention (R14 version, unchanged — measured 185 µs).
// grid (NN/QT, H, NSPLIT), 128 threads.
// ---------------------------------------------------------------------------
__global__ __launch_bounds__(128)
void attn_kernel()
{
    extern __shared__ __align__(16) uint8_t smem[];

    const int tid  = threadIdx.x;
    const int wid  = tid >> 5;
    const int lane = tid & 31;
    const int h    = blockIdx.y;
    const int s    = blockIdx.z;
    const int q0   = blockIdx.x * QT;

    const uint32_t sbase = smem_u32(smem);

    for (int u = tid; u < 128 * 10; u += 128) {
        int row = u / 10, w = u - row * 10;
        uint32_t off = row * KSTRIDE + w * 16;
        *(uint4*)(smem + off)         = ((const uint4*)&g_Qe[0][h][q0 + row][0])[w];
        *(uint4*)(smem + 22528 + off) = ((const uint4*)&g_Qe[1][h][q0 + row][0])[w];
    }
    __syncthreads();

    uint32_t qh[2][5][4], ql[2][5][4];
#pragma unroll
    for (int r = 0; r < 2; r++) {
        uint32_t qoff = (wid * 32 + r * 16 + (lane & 15)) * KSTRIDE + (lane >> 4) * 16;
#pragma unroll
        for (int ks = 0; ks < 5; ks++) {
            ldm_x4(qh[r][ks], sbase + qoff + ks * 32);
            ldm_x4(ql[r][ks], sbase + 22528 + qoff + ks * 32);
        }
    }
    __syncthreads();

    const int hl = (lane >> 4) & 1;
    uint32_t kb[2], vb[2];
#pragma unroll
    for (int st = 0; st < 2; st++) {
        kb[st] = sbase + st * STAGE_BYTES + (hl ? KB_HL : 0)
               + (lane & 7) * KSTRIDE + ((lane >> 3) & 1) * 16;
        vb[st] = sbase + st * STAGE_BYTES + 2 * KB_HL + (hl ? VB_HL : 0)
               + (lane & 7) * VSTRIDE + ((lane >> 3) & 1) * 16;
    }

    auto prefetch = [&](int tt, int st) {
        const int j0 = tt * KT;
        const uint32_t kB = sbase + st * STAGE_BYTES;
        for (int u = tid; u < 64 * 10; u += 128) {
            int row = u / 10, w = u - row * 10;
            uint32_t off = kB + row * KSTRIDE + w * 16;
            cp16(off,          &g_Ke[0][h][j0 + row][w * 8]);
            cp16(off + KB_HL,  &g_Ke[1][h][j0 + row][w * 8]);
        }
        const uint32_t vB = kB + 2 * KB_HL;
        for (int u = tid; u < 64 * 8; u += 128) {
            int row = u >> 3, w = u & 7;
            uint32_t off = vB + row * VSTRIDE + w * 16;
            cp16(off,          &g_Vt[0][h][row][j0 + w * 8]);
            cp16(off + VB_HL,  &g_Vt[1][h][row][j0 + w * 8]);
        }
    };

    float m[2][2], l[2][2];
#pragma unroll
    for (int r = 0; r < 2; r++) { m[r][0] = m[r][1] = -INFINITY; l[r][0] = l[r][1] = 0.f; }
    float o[2][8][4];
#pragma unroll
    for (int r = 0; r < 2; r++)
#pragma unroll
        for (int g = 0; g < 8; g++) { o[r][g][0]=0.f; o[r][g][1]=0.f; o[r][g][2]=0.f; o[r][g][3]=0.f; }

    prefetch(s * NT2, 0);
    CP_COMMIT();

    for (int t = 0; t < NT2; t++) {
        const int cur = t & 1;
        CP_WAIT0();
        __syncthreads();
        if (t + 1 < NT2) {
            prefetch(s * NT2 + t + 1, cur ^ 1);
            CP_COMMIT();
        }

        float c[2][8][4];
#pragma unroll
        for (int r = 0; r < 2; r++)
#pragma unroll
            for (int g = 0; g < 8; g++) { c[r][g][0]=0.f; c[r][g][1]=0.f; c[r][g][2]=0.f; c[r][g][3]=0.f; }
#pragma unroll
        for (int g = 0; g < 8; g++) {
            uint32_t base = kb[cur] + g * 8 * KSTRIDE;
#pragma unroll
            for (int ks = 0; ks < 5; ks++) {
                uint32_t b[4];
                ldm_x4(b, base + ks * 32);
#pragma unroll
                for (int r = 0; r < 2; r++) {
                    mma16816(c[r][g], qh[r][ks], b[0], b[1]);
                    mma16816(c[r][g], ql[r][ks], b[0], b[1]);
                    mma16816(c[r][g], qh[r][ks], b[2], b[3]);
                }
            }
        }

        bool upd = false;
        float mn[2][2];
#pragma unroll
        for (int r = 0; r < 2; r++) {
            float r0 = -INFINITY, r1 = -INFINITY;
#pragma unroll
            for (int g = 0; g < 8; g++) {
                r0 = fmaxf(r0, fmaxf(c[r][g][0], c[r][g][1]));
                r1 = fmaxf(r1, fmaxf(c[r][g][2], c[r][g][3]));
            }
            r0 = fmaxf(r0, __shfl_xor_sync(0xffffffffu, r0, 1));
            r0 = fmaxf(r0, __shfl_xor_sync(0xffffffffu, r0, 2));
            r1 = fmaxf(r1, __shfl_xor_sync(0xffffffffu, r1, 1));
            r1 = fmaxf(r1, __shfl_xor_sync(0xffffffffu, r1, 2));
            mn[r][0] = fmaxf(m[r][0], r0);
            mn[r][1] = fmaxf(m[r][1], r1);
            upd |= (mn[r][0] > m[r][0]) | (mn[r][1] > m[r][1]);
        }
        if (__any_sync(0xffffffffu, upd)) {
#pragma unroll
            for (int r = 0; r < 2; r++) {
                float sc0 = ex2(m[r][0] - mn[r][0]);
                float sc1 = ex2(m[r][1] - mn[r][1]);
                l[r][0] *= sc0; l[r][1] *= sc1;
#pragma unroll
                for (int g = 0; g < 8; g++) {
                    o[r][g][0] *= sc0; o[r][g][1] *= sc0;
                    o[r][g][2] *= sc1; o[r][g][3] *= sc1;
                }
            }
        }
#pragma unroll
        for (int r = 0; r < 2; r++) { m[r][0] = mn[r][0]; m[r][1] = mn[r][1]; }

        uint32_t ph[2][4][4];
#pragma unroll
        for (int r = 0; r < 2; r++) {
            float ls0 = 0.f, ls1 = 0.f;
#pragma unroll
            for (int g = 0; g < 8; g++) {
                c[r][g][0] = ex2(c[r][g][0] - m[r][0]);
                c[r][g][1] = ex2(c[r][g][1] - m[r][0]);
                c[r][g][2] = ex2(c[r][g][2] - m[r][1]);
                c[r][g][3] = ex2(c[r][g][3] - m[r][1]);
                ls0 += c[r][g][0] + c[r][g][1];
                ls1 += c[r][g][2] + c[r][g][3];
            }
            l[r][0] += ls0;
            l[r][1] += ls1;
#pragma unroll
            for (int kk = 0; kk < 4; kk++) {
                ph[r][kk][0] = pack_bf16x2(c[r][2*kk][0],   c[r][2*kk][1]);
                ph[r][kk][1] = pack_bf16x2(c[r][2*kk][2],   c[r][2*kk][3]);
                ph[r][kk][2] = pack_bf16x2(c[r][2*kk+1][0], c[r][2*kk+1][1]);
                ph[r][kk][3] = pack_bf16x2(c[r][2*kk+1][2], c[r][2*kk+1][3]);
            }
        }

#pragma unroll
        for (int g = 0; g < 8; g++) {
            uint32_t base = vb[cur] + g * 8 * VSTRIDE;
#pragma unroll
            for (int kk = 0; kk < 4; kk++) {
                uint32_t v[4];
                ldm_x4(v, base + kk * 32);
#pragma unroll
                for (int r = 0; r < 2; r++) {
                    mma16816(o[r][g], ph[r][kk], v[0], v[1]);
                    mma16816(o[r][g], ph[r][kk], v[2], v[3]);
                }
            }
        }
    }

#pragma unroll
    for (int r = 0; r < 2; r++) {
        l[r][0] += __shfl_xor_sync(0xffffffffu, l[r][0], 1);
        l[r][0] += __shfl_xor_sync(0xffffffffu, l[r][0], 2);
        l[r][1] += __shfl_xor_sync(0xffffffffu, l[r][1], 1);
        l[r][1] += __shfl_xor_sync(0xffffffffu, l[r][1], 2);

        const int r0row = q0 + wid * 32 + r * 16 + (lane >> 2);
        const int r1row = r0row + 8;
        if ((lane & 3) == 0) {
            g_pm[(s * H + h) * NN + r0row] = m[r][0];
            g_pm[(s * H + h) * NN + r1row] = m[r][1];
            g_pl[(s * H + h) * NN + r0row] = l[r][0];
            g_pl[(s * H + h) * NN + r1row] = l[r][1];
        }
        const int dcol = 2 * (lane & 3);
#pragma unroll
        for (int g = 0; g < 8; g++) {
            int d = 8 * g + dcol;
            *reinterpret_cast<float2*>(&g_pO[s][h][r0row][d]) = make_float2(o[r][g][0], o[r][g][1]);
            *reinterpret_cast<float2*>(&g_pO[s][h][r1row][d]) = make_float2(o[r][g][2], o[r][g][3]);
        }
    }
}

// ---------------------------------------------------------------------------
// Kernel 3: fused combine + output projection (unchanged).
// ---------------------------------------------------------------------------
#define TPB_TOK 16

__global__ __launch_bounds__(256)
void epilogue_kernel(const float* __restrict__ W_ao, const float* __restrict__ W_vo,
                     float* __restrict__ out)
{
    __shared__ float s_aoT[H * CHAN * ADIM];
    __shared__ float s_voT[H * CHAN * VDIM];
    __shared__ float sO[H][TPB_TOK][D + 1];
    __shared__ float sW[H][TPB_TOK][NSPLIT];

    const int tid = threadIdx.x;
    const int n0  = blockIdx.x * TPB_TOK;
    const int HN  = H * NN;

    for (int t = tid; t < H * ADIM * CHAN; t += 256) {
        int hh = t >> 10, j = (t >> 4) & 63, i = t & 15;
        s_aoT[(hh * CHAN + i) * ADIM + j] = W_ao[t];
    }
    for (int t = tid; t < H * VDIM * CHAN; t += 256) {
        int hh = t >> 8, j = (t >> 4) & 15, cc = t & 15;
        s_voT[(hh * CHAN + cc) * VDIM + j] = W_vo[t];
    }

    if (tid < H * TPB_TOK) {
        const int hh = tid >> 4, nl = tid & 15;
        const int gid = hh * NN + n0 + nl;
        float mm[NSPLIT], ll[NSPLIT];
        float M = -INFINITY;
#pragma unroll
        for (int sp = 0; sp < NSPLIT; sp++) {
            mm[sp] = g_pm[sp * HN + gid];
            ll[sp] = g_pl[sp * HN + gid];
            M = fmaxf(M, mm[sp]);
        }
        float lsum = 0.f;
        float w[NSPLIT];
#pragma unroll
        for (int sp = 0; sp < NSPLIT; sp++) {
            w[sp] = ex2(mm[sp] - M);
            lsum += w[sp] * ll[sp];
        }
        float inv = 1.0f / (lsum * 64.0f);   // 64 = sqrt(4096)
#pragma unroll
        for (int sp = 0; sp < NSPLIT; sp++) sW[hh][nl][sp] = w[sp] * inv;
    }
    __syncthreads();

    for (int u = tid; u < H * TPB_TOK * (D / 4); u += 256) {
        const int hh = u >> 8, nl = (u >> 4) & 15, dq = u & 15;
        const int n = n0 + nl;
        float a0 = 0.f, a1 = 0.f, a2 = 0.f, a3 = 0.f;
#pragma unroll
        for (int sp = 0; sp < NSPLIT; sp++) {
            float4 x = ((const float4*)&g_pO[sp][hh][n][0])[dq];
            float w = sW[hh][nl][sp];
            a0 += w * x.x; a1 += w * x.y; a2 += w * x.z; a3 += w * x.w;
        }
        sO[hh][nl][4*dq+0] = a0;
        sO[hh][nl][4*dq+1] = a1;
        sO[hh][nl][4*dq+2] = a2;
        sO[hh][nl][4*dq+3] = a3;
    }
    __syncthreads();

    for (int q = tid; q < TPB_TOK * (16 + 12); q += 256) {
        if (q < 256) {
            const int nl = q >> 4, jq = q & 15;
            float a0 = 0.f, a1 = 0.f, a2 = 0.f, a3 = 0.f;
#pragma unroll
            for (int hh = 0; hh < H; hh++) {
#pragma unroll
                for (int i = 0; i < CHAN; i++) {
                    float oi = sO[hh][nl][i];
                    const float4 w = *(const float4*)&s_aoT[(hh * CHAN + i) * ADIM + 4*jq];
                    a0 += w.x * oi; a1 += w.y * oi; a2 += w.z * oi; a3 += w.w * oi;
                }
            }
            *(float4*)&out[(size_t)(n0 + nl) * ADIM + 4*jq] = make_float4(a0, a1, a2, a3);
        } else {
            const int qq = q - 256;
            const int nl = qq / 12, vq = qq - nl * 12;
            float acc[4];
#pragma unroll
            for (int e = 0; e < 4; e++) {
                const int jv = 4 * vq + e;
                const int j = jv / 3, vv = jv - 3 * j;
                float a = 0.f;
#pragma unroll
                for (int hh = 0; hh < H; hh++)
#pragma unroll
                    for (int c = 0; c < CHAN; c++)
                        a += s_voT[(hh * CHAN + c) * VDIM + j] * sO[hh][nl][CHAN + 3*c + vv];
                acc[e] = a;
            }
            *(float4*)&out[(size_t)NN * ADIM + (size_t)(n0 + nl) * 48 + 4*vq] =
                make_float4(acc[0], acc[1], acc[2], acc[3]);
        }
    }
}

// ---------------------------------------------------------------------------
extern "C" void kernel_launch(void* const* d_in, const int* in_sizes, int n_in,
                              void* d_out, int out_size)
{
    const float* ax    = (const float*)d_in[0];
    const float* vx    = (const float*)d_in[1];
    const float* pos_k = (const float*)d_in[2];
    const float* pos_q = (const float*)d_in[3];
    const float* W_aq  = (const float*)d_in[4];
    const float* W_vq  = (const float*)d_in[5];
    const float* W_ak  = (const float*)d_in[6];
    const float* W_vk  = (const float*)d_in[7];
    const float* W_av  = (const float*)d_in[8];
    const float* W_vv  = (const float*)d_in[9];
    const float* W_ao  = (const float*)d_in[10];
    const float* W_vo  = (const float*)d_in[11];
    float* out = (float*)d_out;

    cudaFuncSetAttribute(attn_kernel, cudaFuncAttributeMaxDynamicSharedMemorySize,
                         SMEM_BYTES);

    proj_kernel<<<dim3(NN / PTOK, H), 256>>>(ax, vx, pos_q, pos_k,
                                             W_aq, W_vq, W_ak, W_vk, W_av, W_vv);
    attn_kernel<<<dim3(NN / QT, H, NSPLIT), 128, SMEM_BYTES>>>();
    epilogue_kernel<<<NN / TPB_TOK, 256>>>(W_ao, W_vo, out);
}

// round 17
// speedup vs baseline: 1.0451x; 1.0451x over previous
#include <cuda_runtime.h>
#include <cuda_bf16.h>
#include <cuda_fp16.h>
#include <cstdint>
#include <math.h>

#define H    4
#define NN   4096
#define CHAN 16
#define ADIM 64
#define VDIM 16
#define D    64
#define EXT  80          // 64 feature dims + 5 bias dims + zero pad (5 ksteps of 16)
#define QT   128         // query rows per CTA (32 per warp, 2 rowsets of 16)
#define KT   64          // key tile
#define NSPLIT 2
#define NT2  (NN / KT / NSPLIT)   // 32 tiles per split
#define VROWS 72         // 64 V dims + ones row (64) + zero rows 65..71

#define LOG2E 1.4426950408889634f

// ---------------- device global scratch (no runtime alloc allowed) ----------
__device__ __align__(16) __nv_bfloat16 g_Qe[2][H][NN][EXT];
__device__ __align__(16) __nv_bfloat16 g_Ke[2][H][NN][EXT];
__device__ __align__(16) __half        g_Vt[2][H][VROWS][NN];  // fp16 hi/lo; rows 65-71 stay zero
__device__ float g_pm[NSPLIT * H * NN];
__device__ float g_pl[NSPLIT * H * NN];
__device__ __align__(16) float g_pO[NSPLIT][H][NN][D];

// ---------------- helpers ---------------------------------------------------
__device__ __forceinline__ uint32_t smem_u32(const void* p) {
    uint32_t a;
    asm("{ .reg .u64 t; cvta.to.shared.u64 t, %1; cvt.u32.u64 %0, t; }" : "=r"(a) : "l"(p));
    return a;
}
__device__ __forceinline__ void ldm_x4(uint32_t* r, uint32_t addr) {
    asm volatile("ldmatrix.sync.aligned.m8n8.x4.shared.b16 {%0,%1,%2,%3}, [%4];"
                 : "=r"(r[0]), "=r"(r[1]), "=r"(r[2]), "=r"(r[3]) : "r"(addr));
}
__device__ __forceinline__ void mma16816(float* c, const uint32_t* a,
                                         uint32_t b0, uint32_t b1) {
    asm volatile("mma.sync.aligned.m16n8k16.row.col.f32.bf16.bf16.f32 "
                 "{%0,%1,%2,%3}, {%4,%5,%6,%7}, {%8,%9}, {%0,%1,%2,%3};"
                 : "+f"(c[0]), "+f"(c[1]), "+f"(c[2]), "+f"(c[3])
                 : "r"(a[0]), "r"(a[1]), "r"(a[2]), "r"(a[3]), "r"(b0), "r"(b1));
}
__device__ __forceinline__ void mma16816_f16(float* c, const uint32_t* a,
                                             uint32_t b0, uint32_t b1) {
    asm volatile("mma.sync.aligned.m16n8k16.row.col.f32.f16.f16.f32 "
                 "{%0,%1,%2,%3}, {%4,%5,%6,%7}, {%8,%9}, {%0,%1,%2,%3};"
                 : "+f"(c[0]), "+f"(c[1]), "+f"(c[2]), "+f"(c[3])
                 : "r"(a[0]), "r"(a[1]), "r"(a[2]), "r"(a[3]), "r"(b0), "r"(b1));
}
__device__ __forceinline__ void pack_hilo(float x0, float x1, uint32_t& hi, uint32_t& lo) {
    asm("cvt.rn.bf16x2.f32 %0, %1, %2;" : "=r"(hi) : "f"(x1), "f"(x0));
    float f0 = __uint_as_float(hi << 16);
    float f1 = __uint_as_float(hi & 0xffff0000u);
    asm("cvt.rn.bf16x2.f32 %0, %1, %2;" : "=r"(lo) : "f"(x1 - f1), "f"(x0 - f0));
}
__device__ __forceinline__ void pack_hilo_f16(float x0, float x1, uint32_t& hi, uint32_t& lo) {
    __half2 hh = __floats2half2_rn(x0, x1);
    float f0 = __half2float(__low2half(hh));
    float f1 = __half2float(__high2half(hh));
    __half2 ll = __floats2half2_rn(x0 - f0, x1 - f1);
    hi = *reinterpret_cast<uint32_t*>(&hh);
    lo = *reinterpret_cast<uint32_t*>(&ll);
}
__device__ __forceinline__ uint32_t pack_f16x2(float x0, float x1) {
    uint32_t r;
    asm("cvt.rn.f16x2.f32 %0, %1, %2;" : "=r"(r) : "f"(x1), "f"(x0));
    return r;
}
__device__ __forceinline__ uint32_t ex2_f16x2(uint32_t x) {
    uint32_t y;
    asm("ex2.approx.f16x2 %0, %1;" : "=r"(y) : "r"(x));
    return y;
}
__device__ __forceinline__ float ex2(float x) {
    float y;
    asm("ex2.approx.f32 %0, %1;" : "=f"(y) : "f"(x));
    return y;
}
__device__ __forceinline__ void cp16(uint32_t saddr, const void* gaddr) {
    asm volatile("cp.async.ca.shared.global [%0], [%1], 16;" :: "r"(saddr), "l"(gaddr) : "memory");
}
#define CP_COMMIT() asm volatile("cp.async.commit_group;" ::: "memory")
#define CP_WAIT0()  asm volatile("cp.async.wait_group 0;"  ::: "memory")

#define KSTRIDE 176
#define VSTRIDE 144
#define KB_HL   (64 * KSTRIDE)                 // 11264 per K plane
#define V_PLANE (VROWS * VSTRIDE)              // 10368 per V plane
#define STAGE_BYTES (2 * KB_HL + 2 * V_PLANE)  // 43264
#define SMEM_BYTES  (2 * STAGE_BYTES)          // 86528

// ---------------------------------------------------------------------------
// Kernel 1: projection (R13/R14 version; V packs to fp16 + ones row).
// grid (NN/16, H), 256 threads.
// ---------------------------------------------------------------------------
#define PTOK 16
#define AXP  68
#define VXP  52

__global__ __launch_bounds__(256)
void proj_kernel(const float* __restrict__ ax, const float* __restrict__ vx,
                 const float* __restrict__ pos_q, const float* __restrict__ pos_k,
                 const float* __restrict__ W_aq, const float* __restrict__ W_vq,
                 const float* __restrict__ W_ak, const float* __restrict__ W_vk,
                 const float* __restrict__ W_av, const float* __restrict__ W_vv)
{
    const int h  = blockIdx.y;
    const int n0 = blockIdx.x * PTOK;
    const int tid = threadIdx.x;

    __shared__ __align__(16) float s_wa[CHAN * ADIM];
    __shared__ __align__(16) float s_wv[CHAN * VDIM];
    __shared__ __align__(16) float s_ax[PTOK * AXP];
    __shared__ __align__(16) float s_vx[PTOK * VXP];
    __shared__ float ts[PTOK][68];

    for (int t = tid; t < PTOK * ADIM; t += 256)
        s_ax[(t >> 6) * AXP + (t & 63)] = ax[(size_t)n0 * ADIM + t];
    for (int t = tid; t < PTOK * VDIM * 3; t += 256)
        s_vx[(t / 48) * VXP + (t % 48)] = vx[(size_t)n0 * VDIM * 3 + t];

    const int c  = tid >> 4;
    const int nl = tid & 15;
    const int n  = n0 + nl;

    for (int z = 0; z < 3; z++) {
        const float* Wa = (z == 0) ? W_aq : (z == 1) ? W_ak : W_av;
        const float* Wv = (z == 0) ? W_vq : (z == 1) ? W_vk : W_vv;
        __syncthreads();
        for (int t = tid; t < CHAN * ADIM; t += 256) s_wa[t] = Wa[h * CHAN * ADIM + t];
        for (int t = tid; t < CHAN * VDIM; t += 256) s_wv[t] = Wv[h * CHAN * VDIM + t];
        __syncthreads();

        const float4* a4 = (const float4*)(s_ax + nl * AXP);
        const float4* w4 = (const float4*)(s_wa + c * ADIM);
        float s0 = 0.f;
#pragma unroll
        for (int j = 0; j < ADIM / 4; j++) {
            float4 av = a4[j], wv4 = w4[j];
            s0 += wv4.x * av.x + wv4.y * av.y + wv4.z * av.z + wv4.w * av.w;
        }

        float vr[48];
        {
            const float4* v4 = (const float4*)(s_vx + nl * VXP);
#pragma unroll
            for (int j = 0; j < 12; j++) {
                float4 t = v4[j];
                vr[4*j] = t.x; vr[4*j+1] = t.y; vr[4*j+2] = t.z; vr[4*j+3] = t.w;
            }
        }
        float wvr[16];
        {
            const float4* q4 = (const float4*)(s_wv + c * VDIM);
#pragma unroll
            for (int j = 0; j < 4; j++) {
                float4 t = q4[j];
                wvr[4*j] = t.x; wvr[4*j+1] = t.y; wvr[4*j+2] = t.z; wvr[4*j+3] = t.w;
            }
        }
        float s1 = 0.f, s2 = 0.f, s3 = 0.f;
#pragma unroll
        for (int j = 0; j < VDIM; j++) {
            float w = wvr[j];
            s1 += w * vr[3*j+0]; s2 += w * vr[3*j+1]; s3 += w * vr[3*j+2];
        }

        if (z < 2) {
            float nsq = s0*s0 + s1*s1 + s2*s2 + s3*s3;
            float sc  = rsqrtf(sqrtf(1.0f + nsq));
            if (z == 0) sc *= LOG2E;
            s0 *= sc; s1 *= sc; s2 *= sc; s3 *= sc;
        }

        if (z == 2) {
            ts[nl][4*c+0] = s0; ts[nl][4*c+1] = s1; ts[nl][4*c+2] = s2; ts[nl][4*c+3] = s3;
            __syncthreads();
            for (int u = tid; u < 64 * 8; u += 256) {
                const int d = u >> 3, p = u & 7;
                uint32_t hv, lv;
                pack_hilo_f16(ts[2*p][d], ts[2*p+1][d], hv, lv);
                *(uint32_t*)&g_Vt[0][h][d][n0 + 2*p] = hv;
                *(uint32_t*)&g_Vt[1][h][d][n0 + 2*p] = lv;
            }
            // ones row (64) for l-via-MMA; rows 65-71 remain zero (static init)
            if (tid < PTOK) {
                g_Vt[0][h][64][n0 + tid] = __float2half(1.0f);
                g_Vt[1][h][64][n0 + tid] = __float2half(0.0f);
            }
            continue;
        }

        uint32_t h01, l01, h23, l23;
        pack_hilo(s0, s1, h01, l01);
        pack_hilo(s2, s3, h23, l23);
        __nv_bfloat16* bh = (z == 0) ? &g_Qe[0][h][n][4*c] : &g_Ke[0][h][n][4*c];
        __nv_bfloat16* bl = (z == 0) ? &g_Qe[1][h][n][4*c] : &g_Ke[1][h][n][4*c];
        ((uint2*)bh)[0] = make_uint2(h01, h23);
        ((uint2*)bl)[0] = make_uint2(l01, l23);

        if (tid < PTOK) {
            const int nb = n0 + tid;
            float e[16];
#pragma unroll
            for (int j = 0; j < 16; j++) e[j] = 0.f;
            const float invr = 1.0f / (float)(1 << (2 * h));
            if (z == 0) {
                const float* pq = pos_q + (h * NN + nb) * 3;
                e[0] = 2.f * invr * pq[0] * LOG2E;
                e[1] = 2.f * invr * pq[1] * LOG2E;
                e[2] = 2.f * invr * pq[2] * LOG2E;
                e[3] = -invr * LOG2E;
                e[4] = -invr * LOG2E;
            } else {
                const float* pk = pos_k + (h * NN + nb) * 3;
                e[0] = pk[0]; e[1] = pk[1]; e[2] = pk[2];
                float w = pk[0]*pk[0] + pk[1]*pk[1] + pk[2]*pk[2];
                float whi = __bfloat162float(__float2bfloat16(w));
                e[3] = whi;
                e[4] = w - whi;
            }
            uint32_t ehw[8], elw[8];
#pragma unroll
            for (int p = 0; p < 8; p++) pack_hilo(e[2*p], e[2*p+1], ehw[p], elw[p]);
            __nv_bfloat16* xh = (z == 0) ? &g_Qe[0][h][nb][64] : &g_Ke[0][h][nb][64];
            __nv_bfloat16* xl = (z == 0) ? &g_Qe[1][h][nb][64] : &g_Ke[1][h][nb][64];
            ((uint4*)xh)[0] = ((const uint4*)ehw)[0]; ((uint4*)xh)[1] = ((const uint4*)ehw)[1];
            ((uint4*)xl)[0] = ((const uint4*)elw)[0]; ((uint4*)xl)[1] = ((const uint4*)elw)[1];
        }
    }
}

// ---------------------------------------------------------------------------
// Kernel 2: HMMA flash attention; f16x2 exp, l via ones-row MMA, fp16 PV.
// grid (NN/QT, H, NSPLIT), 128 threads.
// ---------------------------------------------------------------------------
__global__ __launch_bounds__(128)
void attn_kernel()
{
    extern __shared__ __align__(16) uint8_t smem[];

    const int tid  = threadIdx.x;
    const int wid  = tid >> 5;
    const int lane = tid & 31;
    const int h    = blockIdx.y;
    const int s    = blockIdx.z;
    const int q0   = blockIdx.x * QT;

    const uint32_t sbase = smem_u32(smem);

    for (int u = tid; u < 128 * 10; u += 128) {
        int row = u / 10, w = u - row * 10;
        uint32_t off = row * KSTRIDE + w * 16;
        *(uint4*)(smem + off)         = ((const uint4*)&g_Qe[0][h][q0 + row][0])[w];
        *(uint4*)(smem + 22528 + off) = ((const uint4*)&g_Qe[1][h][q0 + row][0])[w];
    }
    __syncthreads();

    uint32_t qh[2][5][4], ql[2][5][4];
#pragma unroll
    for (int r = 0; r < 2; r++) {
        uint32_t qoff = (wid * 32 + r * 16 + (lane & 15)) * KSTRIDE + (lane >> 4) * 16;
#pragma unroll
        for (int ks = 0; ks < 5; ks++) {
            ldm_x4(qh[r][ks], sbase + qoff + ks * 32);
            ldm_x4(ql[r][ks], sbase + 22528 + qoff + ks * 32);
        }
    }
    __syncthreads();

    const int hl = (lane >> 4) & 1;
    uint32_t kb[2], vb[2];
#pragma unroll
    for (int st = 0; st < 2; st++) {
        kb[st] = sbase + st * STAGE_BYTES + (hl ? KB_HL : 0)
               + (lane & 7) * KSTRIDE + ((lane >> 3) & 1) * 16;
        vb[st] = sbase + st * STAGE_BYTES + 2 * KB_HL + (hl ? V_PLANE : 0)
               + (lane & 7) * VSTRIDE + ((lane >> 3) & 1) * 16;
    }

    auto prefetch = [&](int tt, int st) {
        const int j0 = tt * KT;
        const uint32_t kB = sbase + st * STAGE_BYTES;
        for (int u = tid; u < 64 * 10; u += 128) {
            int row = u / 10, w = u - row * 10;
            uint32_t off = kB + row * KSTRIDE + w * 16;
            cp16(off,          &g_Ke[0][h][j0 + row][w * 8]);
            cp16(off + KB_HL,  &g_Ke[1][h][j0 + row][w * 8]);
        }
        const uint32_t vB = kB + 2 * KB_HL;
        for (int u = tid; u < VROWS * 8; u += 128) {
            int row = u >> 3, w = u & 7;
            uint32_t off = vB + row * VSTRIDE + w * 16;
            cp16(off,           &g_Vt[0][h][row][j0 + w * 8]);
            cp16(off + V_PLANE, &g_Vt[1][h][row][j0 + w * 8]);
        }
    };

    float m[2][2];
#pragma unroll
    for (int r = 0; r < 2; r++) { m[r][0] = -INFINITY; m[r][1] = -INFINITY; }
    float o[2][9][4];   // groups 0..7 = O dims; group 8 col 64 = running l
#pragma unroll
    for (int r = 0; r < 2; r++)
#pragma unroll
        for (int g = 0; g < 9; g++) { o[r][g][0]=0.f; o[r][g][1]=0.f; o[r][g][2]=0.f; o[r][g][3]=0.f; }

    prefetch(s * NT2, 0);
    CP_COMMIT();

    for (int t = 0; t < NT2; t++) {
        const int cur = t & 1;
        CP_WAIT0();
        __syncthreads();
        if (t + 1 < NT2) {
            prefetch(s * NT2 + t + 1, cur ^ 1);
            CP_COMMIT();
        }

        float c[2][8][4];
#pragma unroll
        for (int r = 0; r < 2; r++)
#pragma unroll
            for (int g = 0; g < 8; g++) { c[r][g][0]=0.f; c[r][g][1]=0.f; c[r][g][2]=0.f; c[r][g][3]=0.f; }
#pragma unroll
        for (int g = 0; g < 8; g++) {
            uint32_t base = kb[cur] + g * 8 * KSTRIDE;
#pragma unroll
            for (int ks = 0; ks < 5; ks++) {
                uint32_t b[4];
                ldm_x4(b, base + ks * 32);
#pragma unroll
                for (int r = 0; r < 2; r++) {
                    mma16816(c[r][g], qh[r][ks], b[0], b[1]);
                    mma16816(c[r][g], ql[r][ks], b[0], b[1]);
                    mma16816(c[r][g], qh[r][ks], b[2], b[3]);
                }
            }
        }

        // ---- online softmax (log2 domain) ----
        bool upd = false;
        float mn[2][2];
#pragma unroll
        for (int r = 0; r < 2; r++) {
            float r0 = -INFINITY, r1 = -INFINITY;
#pragma unroll
            for (int g = 0; g < 8; g++) {
                r0 = fmaxf(r0, fmaxf(c[r][g][0], c[r][g][1]));
                r1 = fmaxf(r1, fmaxf(c[r][g][2], c[r][g][3]));
            }
            r0 = fmaxf(r0, __shfl_xor_sync(0xffffffffu, r0, 1));
            r0 = fmaxf(r0, __shfl_xor_sync(0xffffffffu, r0, 2));
            r1 = fmaxf(r1, __shfl_xor_sync(0xffffffffu, r1, 1));
            r1 = fmaxf(r1, __shfl_xor_sync(0xffffffffu, r1, 2));
            mn[r][0] = fmaxf(m[r][0], r0);
            mn[r][1] = fmaxf(m[r][1], r1);
            upd |= (mn[r][0] > m[r][0]) | (mn[r][1] > m[r][1]);
        }
        if (__any_sync(0xffffffffu, upd)) {
#pragma unroll
            for (int r = 0; r < 2; r++) {
                float sc0 = ex2(m[r][0] - mn[r][0]);
                float sc1 = ex2(m[r][1] - mn[r][1]);
#pragma unroll
                for (int g = 0; g < 9; g++) {        // includes l column
                    o[r][g][0] *= sc0; o[r][g][1] *= sc0;
                    o[r][g][2] *= sc1; o[r][g][3] *= sc1;
                }
            }
        }
#pragma unroll
        for (int r = 0; r < 2; r++) { m[r][0] = mn[r][0]; m[r][1] = mn[r][1]; }

        // ---- P = 2^(c-m) via f16x2 MUFU; result IS the fp16 A-frag ----
        uint32_t ph[2][4][4];
#pragma unroll
        for (int r = 0; r < 2; r++) {
            const float m0 = m[r][0], m1 = m[r][1];
#pragma unroll
            for (int kk = 0; kk < 4; kk++) {
                ph[r][kk][0] = ex2_f16x2(pack_f16x2(c[r][2*kk][0] - m0,   c[r][2*kk][1] - m0));
                ph[r][kk][1] = ex2_f16x2(pack_f16x2(c[r][2*kk][2] - m1,   c[r][2*kk][3] - m1));
                ph[r][kk][2] = ex2_f16x2(pack_f16x2(c[r][2*kk+1][0] - m0, c[r][2*kk+1][1] - m0));
                ph[r][kk][3] = ex2_f16x2(pack_f16x2(c[r][2*kk+1][2] - m1, c[r][2*kk+1][3] - m1));
            }
        }

        // ---- O += P @ V^T (fp16): groups 0..7 hi+lo, group 8 (ones) hi only ----
#pragma unroll
        for (int g = 0; g < 9; g++) {
            uint32_t base = vb[cur] + g * 8 * VSTRIDE;
#pragma unroll
            for (int kk = 0; kk < 4; kk++) {
                uint32_t v[4];
                ldm_x4(v, base + kk * 32);
#pragma unroll
                for (int r = 0; r < 2; r++) {
                    mma16816_f16(o[r][g], ph[r][kk], v[0], v[1]);
                    if (g < 8) mma16816_f16(o[r][g], ph[r][kk], v[2], v[3]);
                }
            }
        }
    }

    // ---- epilogue: l lives in o[.][8] col 64 ----
#pragma unroll
    for (int r = 0; r < 2; r++) {
        const int r0row = q0 + wid * 32 + r * 16 + (lane >> 2);
        const int r1row = r0row + 8;
        if ((lane & 3) == 0) {
            g_pm[(s * H + h) * NN + r0row] = m[r][0];
            g_pm[(s * H + h) * NN + r1row] = m[r][1];
            g_pl[(s * H + h) * NN + r0row] = o[r][8][0];
            g_pl[(s * H + h) * NN + r1row] = o[r][8][2];
        }
        const int dcol = 2 * (lane & 3);
#pragma unroll
        for (int g = 0; g < 8; g++) {
            int d = 8 * g + dcol;
            *reinterpret_cast<float2*>(&g_pO[s][h][r0row][d]) = make_float2(o[r][g][0], o[r][g][1]);
            *reinterpret_cast<float2*>(&g_pO[s][h][r1row][d]) = make_float2(o[r][g][2], o[r][g][3]);
        }
    }
}

// ---------------------------------------------------------------------------
// Kernel 3: fused combine + output projection (R14 version, unchanged).
// ---------------------------------------------------------------------------
#define TPB_TOK 16

__global__ __launch_bounds__(256)
void epilogue_kernel(const float* __restrict__ W_ao, const float* __restrict__ W_vo,
                     float* __restrict__ out)
{
    __shared__ float s_aoT[H * CHAN * ADIM];
    __shared__ float s_voT[H * CHAN * VDIM];
    __shared__ float sO[H][TPB_TOK][D + 1];
    __shared__ float sW[H][TPB_TOK][NSPLIT];

    const int tid = threadIdx.x;
    const int n0  = blockIdx.x * TPB_TOK;
    const int HN  = H * NN;

    for (int t = tid; t < H * ADIM * CHAN; t += 256) {
        int hh = t >> 10, j = (t >> 4) & 63, i = t & 15;
        s_aoT[(hh * CHAN + i) * ADIM + j] = W_ao[t];
    }
    for (int t = tid; t < H * VDIM * CHAN; t += 256) {
        int hh = t >> 8, j = (t >> 4) & 15, cc = t & 15;
        s_voT[(hh * CHAN + cc) * VDIM + j] = W_vo[t];
    }

    if (tid < H * TPB_TOK) {
        const int hh = tid >> 4, nl = tid & 15;
        const int gid = hh * NN + n0 + nl;
        float mm[NSPLIT], ll[NSPLIT];
        float M = -INFINITY;
#pragma unroll
        for (int sp = 0; sp < NSPLIT; sp++) {
            mm[sp] = g_pm[sp * HN + gid];
            ll[sp] = g_pl[sp * HN + gid];
            M = fmaxf(M, mm[sp]);
        }
        float lsum = 0.f;
        float w[NSPLIT];
#pragma unroll
        for (int sp = 0; sp < NSPLIT; sp++) {
            w[sp] = ex2(mm[sp] - M);
            lsum += w[sp] * ll[sp];
        }
        float inv = 1.0f / (lsum * 64.0f);   // 64 = sqrt(4096)
#pragma unroll
        for (int sp = 0; sp < NSPLIT; sp++) sW[hh][nl][sp] = w[sp] * inv;
    }
    __syncthreads();

    for (int u = tid; u < H * TPB_TOK * (D / 4); u += 256) {
        const int hh = u >> 8, nl = (u >> 4) & 15, dq = u & 15;
        const int n = n0 + nl;
        float a0 = 0.f, a1 = 0.f, a2 = 0.f, a3 = 0.f;
#pragma unroll
        for (int sp = 0; sp < NSPLIT; sp++) {
            float4 x = ((const float4*)&g_pO[sp][hh][n][0])[dq];
            float w = sW[hh][nl][sp];
            a0 += w * x.x; a1 += w * x.y; a2 += w * x.z; a3 += w * x.w;
        }
        sO[hh][nl][4*dq+0] = a0;
        sO[hh][nl][4*dq+1] = a1;
        sO[hh][nl][4*dq+2] = a2;
        sO[hh][nl][4*dq+3] = a3;
    }
    __syncthreads();

    for (int q = tid; q < TPB_TOK * (16 + 12); q += 256) {
        if (q < 256) {
            const int nl = q >> 4, jq = q & 15;
            float a0 = 0.f, a1 = 0.f, a2 = 0.f, a3 = 0.f;
#pragma unroll
            for (int hh = 0; hh < H; hh++) {
#pragma unroll
                for (int i = 0; i < CHAN; i++) {
                    float oi = sO[hh][nl][i];
                    const float4 w = *(const float4*)&s_aoT[(hh * CHAN + i) * ADIM + 4*jq];
                    a0 += w.x * oi; a1 += w.y * oi; a2 += w.z * oi; a3 += w.w * oi;
                }
            }
            *(float4*)&out[(size_t)(n0 + nl) * ADIM + 4*jq] = make_float4(a0, a1, a2, a3);
        } else {
            const int qq = q - 256;
            const int nl = qq / 12, vq = qq - nl * 12;
            float acc[4];
#pragma unroll
            for (int e = 0; e < 4; e++) {
                const int jv = 4 * vq + e;
                const int j = jv / 3, vv = jv - 3 * j;
                float a = 0.f;
#pragma unroll
                for (int hh = 0; hh < H; hh++)
#pragma unroll
                    for (int c = 0; c < CHAN; c++)
                        a += s_voT[(hh * CHAN + c) * VDIM + j] * sO[hh][nl][CHAN + 3*c + vv];
                acc[e] = a;
            }
            *(float4*)&out[(size_t)NN * ADIM + (size_t)(n0 + nl) * 48 + 4*vq] =
                make_float4(acc[0], acc[1], acc[2], acc[3]);
        }
    }
}

// ---------------------------------------------------------------------------
extern "C" void kernel_launch(void* const* d_in, const int* in_sizes, int n_in,
                              void* d_out, int out_size)
{
    const float* ax    = (const float*)d_in[0];
    const float* vx    = (const float*)d_in[1];
    const float* pos_k = (const float*)d_in[2];
    const float* pos_q = (const float*)d_in[3];
    const float* W_aq  = (const float*)d_in[4];
    const float* W_vq  = (const float*)d_in[5];
    const float* W_ak  = (const float*)d_in[6];
    const float* W_vk  = (const float*)d_in[7];
    const float* W_av  = (const float*)d_in[8];
    const float* W_vv  = (const float*)d_in[9];
    const float* W_ao  = (const float*)d_in[10];
    const float* W_vo  = (const float*)d_in[11];
    float* out = (float*)d_out;

    cudaFuncSetAttribute(attn_kernel, cudaFuncAttributeMaxDynamicSharedMemorySize,
                         SMEM_BYTES);

    proj_kernel<<<dim3(NN / PTOK, H), 256>>>(ax, vx, pos_q, pos_k,
                                             W_aq, W_vq, W_ak, W_vk, W_av, W_vv);
    attn_kernel<<<dim3(NN / QT, H, NSPLIT), 128, SMEM_BYTES>>>();
    epilogue_kernel<<<NN / TPB_TOK, 256>>>(W_ao, W_vo, out);
}